// round 15
// baseline (speedup 1.0000x reference)
#include <cuda_runtime.h>
#include <cuda_fp16.h>
#include <cstdint>
#include <math.h>

// ---------------------------------------------------------------------------
// KoopmanAE, mma.sync FP16 + ldmatrix. R15 experiment: CTA tile 256x128x64,
// 8 warps of 64x64 (warp grid 4m x 2n), cp.async 4-stage, occ 1.
// Crossbar demand 86 B/cyc (vs 125 at 128x128/occ2) -- discriminates whether
// the fp16 tensor rate (1024 vs 2048 MAC/cyc/SM) or the crossbar was binding.
// ---------------------------------------------------------------------------

#define BM 256
#define BN 128
#define BK 64
#define STAGES 4
#define THREADS 256

#define ALDB 144                              // row stride bytes (64 halves + 8 pad)
#define STAGE_A_BYTES (256 * ALDB)            // 36864
#define STAGE_B_BYTES (128 * ALDB)            // 18432
#define STAGE_BYTES (STAGE_A_BYTES + STAGE_B_BYTES)   // 55296
#define SMEM_DYN (STAGES * STAGE_BYTES)       // 221184

__device__ __half g_h[8192u * 4096u];
__device__ __half g_xh[8192u * 4096u];
__device__ __half g_encr[8192u * 2048u];
__device__ __half g_wt[4096u*4096u + 4096u*2048u + 2048u*4096u + 4096u*4096u];

// ---------------- helpers ----------------
__device__ __forceinline__ uint32_t smem_u32(const void* p) {
    uint32_t a;
    asm("{ .reg .u64 t; cvta.to.shared.u64 t, %1; cvt.u32.u64 %0, t; }" : "=r"(a) : "l"(p));
    return a;
}
__device__ __forceinline__ void cp16(uint32_t dst, const void* src) {
    asm volatile("cp.async.cg.shared.global [%0], [%1], 16;" :: "r"(dst), "l"(src));
}
#define CP_COMMIT() asm volatile("cp.async.commit_group;" ::: "memory")
#define CP_WAIT(n)  asm volatile("cp.async.wait_group %0;" :: "n"(n) : "memory")

__device__ __forceinline__ void ldsm4(uint32_t& r0, uint32_t& r1, uint32_t& r2,
                                      uint32_t& r3, uint32_t addr) {
    asm volatile("ldmatrix.sync.aligned.m8n8.x4.shared.b16 {%0,%1,%2,%3}, [%4];"
                 : "=r"(r0), "=r"(r1), "=r"(r2), "=r"(r3) : "r"(addr));
}

__device__ __forceinline__ void mma_f16(float d[4], const uint32_t a[4],
                                        uint32_t b0, uint32_t b1) {
    asm("mma.sync.aligned.m16n8k16.row.col.f32.f16.f16.f32 "
        "{%0,%1,%2,%3}, {%4,%5,%6,%7}, {%8,%9}, {%0,%1,%2,%3};"
        : "+f"(d[0]), "+f"(d[1]), "+f"(d[2]), "+f"(d[3])
        : "r"(a[0]), "r"(a[1]), "r"(a[2]), "r"(a[3]), "r"(b0), "r"(b1));
}

// ---------------- pre-passes (unchanged from R14) ----------------
__global__ void transpose_half(const float* __restrict__ W, __half* __restrict__ WT,
                               int K, int N) {
    __shared__ float t[64][33];
    const int nb = blockIdx.x * 32, kb = blockIdx.y * 64;
    const int tx = threadIdx.x, ty = threadIdx.y;
#pragma unroll
    for (int i = 0; i < 64; i += 8)
        t[ty + i][tx] = W[(size_t)(kb + ty + i) * N + nb + tx];
    __syncthreads();
#pragma unroll
    for (int i = 0; i < 32; i += 8) {
        const int n = nb + ty + i;
        __half2 v = __floats2half2_rn(t[2 * tx][ty + i], t[2 * tx + 1][ty + i]);
        *(__half2*)(WT + (size_t)n * K + kb + 2 * tx) = v;
    }
}

__global__ void half_copy(const float* __restrict__ in, __half* __restrict__ out, int n4) {
    int i = blockIdx.x * blockDim.x + threadIdx.x;
    if (i < n4) {
        float4 v = ((const float4*)in)[i];
        __half2* o = (__half2*)(out + (size_t)i * 4);
        o[0] = __floats2half2_rn(v.x, v.y);
        o[1] = __floats2half2_rn(v.z, v.w);
    }
}

// ---------------- GEMM ----------------
// MODE 0: Ch = (half)tanh(acc+bias)
// MODE 1: Cf = acc+bias (enc_x), C2 = rotate (enc_pred), CR = (half)C2
// MODE 2: Cf = acc+bias
template <int MODE, int N, int K>
__global__ void __launch_bounds__(THREADS, 1)
gemm_f16(const __half* __restrict__ A, const __half* __restrict__ WT,
         const float* __restrict__ bias, void* __restrict__ Cv,
         float* __restrict__ C2, __half* __restrict__ CR,
         const float* __restrict__ dt, const float* __restrict__ amps,
         const float* __restrict__ freqs)
{
    extern __shared__ char sm[];
    const uint32_t sm_base = smem_u32(sm);

    const int tid    = threadIdx.x;
    const int wid    = tid >> 5;
    const int lane   = tid & 31;
    const int g      = lane >> 2;
    const int t      = lane & 3;
    const int warp_m = wid >> 1;   // 0..3 : 64 rows each
    const int warp_n = wid & 1;    // 0..1 : 64 cols each
    const int bm = blockIdx.y;
    const int bn = blockIdx.x;
    constexpr int KT = K / BK;

    // cp.async mapping: A 8 chunks (256 rows), B 4 chunks (128 rows)
    const int rowc = tid >> 3;            // 0..31
    const int chnk = tid & 7;             // 0..7 (16B chunks within 128B row)
    const __half* baseA = A  + (size_t)(bm * BM + rowc) * K + chnk * 8;
    const __half* baseB = WT + (size_t)(bn * BN + rowc) * K + chnk * 8;
    const uint32_t dA0 = (uint32_t)(rowc * ALDB + chnk * 16);
    const uint32_t dB0 = (uint32_t)(STAGE_A_BYTES + rowc * ALDB + chnk * 16);

    // ldmatrix per-lane base offsets (bytes)
    const uint32_t a_lmb = (uint32_t)((warp_m * 64 + ((lane >> 3) & 1) * 8 + (lane & 7)) * ALDB
                                      + (lane >> 4) * 16);
    const uint32_t b_lmb = (uint32_t)(STAGE_A_BYTES
                                      + (warp_n * 64 + (lane >> 4) * 8 + (lane & 7)) * ALDB
                                      + ((lane >> 3) & 1) * 16);

    // prefetch STAGES-1 tiles
#pragma unroll
    for (int p = 0; p < STAGES - 1; ++p) {
        const uint32_t sb = sm_base + p * STAGE_BYTES;
        const int ko = p * BK;
#pragma unroll
        for (int i = 0; i < 8; ++i)
            cp16(sb + dA0 + i * (32 * ALDB), baseA + (size_t)i * 32 * K + ko);
#pragma unroll
        for (int i = 0; i < 4; ++i)
            cp16(sb + dB0 + i * (32 * ALDB), baseB + (size_t)i * 32 * K + ko);
        CP_COMMIT();
    }

    float acc[4][8][4];
#pragma unroll
    for (int mi = 0; mi < 4; ++mi)
#pragma unroll
        for (int ni = 0; ni < 8; ++ni)
#pragma unroll
            for (int r = 0; r < 4; ++r) acc[mi][ni][r] = 0.0f;

    int stage_idx = 0;
    int write_idx = STAGES - 1;

    for (int kt = 0; kt < KT; ++kt) {
        CP_WAIT(STAGES - 2);
        __syncthreads();

        const int nt = kt + STAGES - 1;
        const bool ld = nt < KT;
        const uint32_t sb = sm_base + write_idx * STAGE_BYTES;
        const int ko = nt * BK;

        const uint32_t st_u = sm_base + stage_idx * STAGE_BYTES;
        const uint32_t a_base = st_u + a_lmb;
        const uint32_t b_base = st_u + b_lmb;

        // ---- 4 k16-slices: 8 ldsm hoisted, 32-MMA chain ----
#pragma unroll
        for (int ks = 0; ks < 4; ++ks) {
            const uint32_t koff = (uint32_t)(ks * 32);
            uint32_t af[4][4];
#pragma unroll
            for (int mi = 0; mi < 4; ++mi)
                ldsm4(af[mi][0], af[mi][1], af[mi][2], af[mi][3],
                      a_base + (uint32_t)(mi * 16 * ALDB) + koff);
            uint32_t bf[4][4];   // 4 pr-groups, each (b00,b01,b10,b11)
#pragma unroll
            for (int pr = 0; pr < 4; ++pr)
                ldsm4(bf[pr][0], bf[pr][1], bf[pr][2], bf[pr][3],
                      b_base + (uint32_t)(pr * 16 * ALDB) + koff);

#pragma unroll
            for (int pr = 0; pr < 4; ++pr)
#pragma unroll
                for (int mi = 0; mi < 4; ++mi) {
                    mma_f16(acc[mi][pr * 2 + 0], af[mi], bf[pr][0], bf[pr][1]);
                    mma_f16(acc[mi][pr * 2 + 1], af[mi], bf[pr][2], bf[pr][3]);
                }

            // spread next-tile cp.async across the MMA stream
            if (ks == 0 && ld) {
#pragma unroll
                for (int i = 0; i < 4; ++i)
                    cp16(sb + dA0 + i * (32 * ALDB), baseA + (size_t)i * 32 * K + ko);
            } else if (ks == 1 && ld) {
#pragma unroll
                for (int i = 4; i < 8; ++i)
                    cp16(sb + dA0 + i * (32 * ALDB), baseA + (size_t)i * 32 * K + ko);
            } else if (ks == 2) {
                if (ld) {
#pragma unroll
                    for (int i = 0; i < 4; ++i)
                        cp16(sb + dB0 + i * (32 * ALDB), baseB + (size_t)i * 32 * K + ko);
                }
                CP_COMMIT();
            }
        }

        if (++stage_idx == STAGES) stage_idx = 0;
        if (++write_idx == STAGES) write_idx = 0;
    }

    // ---- epilogue ----
    const int row_base = bm * BM + warp_m * 64;
    const int col_base = bn * BN + warp_n * 64;

#pragma unroll
    for (int mi = 0; mi < 4; ++mi) {
        const int r0 = row_base + mi * 16 + g;
        const int r1 = r0 + 8;
        float dt0 = 0.f, dt1 = 0.f;
        if (MODE == 1) { dt0 = dt[r0]; dt1 = dt[r1]; }
#pragma unroll
        for (int ni = 0; ni < 8; ++ni) {
            const int c = col_base + ni * 8 + 2 * t;
            const float bv0 = bias[c];
            const float bv1 = bias[c + 1];
            float v00 = acc[mi][ni][0] + bv0;
            float v01 = acc[mi][ni][1] + bv1;
            float v10 = acc[mi][ni][2] + bv0;
            float v11 = acc[mi][ni][3] + bv1;

            if (MODE == 0) {
                __half* Ch = (__half*)Cv;
                *(__half2*)(Ch + (size_t)r0 * N + c) =
                    __floats2half2_rn(tanhf(v00), tanhf(v01));
                *(__half2*)(Ch + (size_t)r1 * N + c) =
                    __floats2half2_rn(tanhf(v10), tanhf(v11));
            } else {
                float* Cf = (float*)Cv;
                *(float2*)(Cf + (size_t)r0 * N + c) = make_float2(v00, v01);
                *(float2*)(Cf + (size_t)r1 * N + c) = make_float2(v10, v11);
            }

            if (MODE == 1) {
                const int f = c >> 1;
                const float af_ = amps[f];
                const float wf = freqs[f];
                {
                    float amp = __powf(af_, dt0);
                    float s, co;
                    sincosf(wf * dt0, &s, &co);
                    float cs = amp * co, ss = amp * s;
                    float e0 = cs * v00 - ss * v01;
                    float e1 = ss * v00 + cs * v01;
                    *(float2*)(C2 + (size_t)r0 * N + c) = make_float2(e0, e1);
                    *(__half2*)(CR + (size_t)r0 * N + c) = __floats2half2_rn(e0, e1);
                }
                {
                    float amp = __powf(af_, dt1);
                    float s, co;
                    sincosf(wf * dt1, &s, &co);
                    float cs = amp * co, ss = amp * s;
                    float e0 = cs * v10 - ss * v11;
                    float e1 = ss * v10 + cs * v11;
                    *(float2*)(C2 + (size_t)r1 * N + c) = make_float2(e0, e1);
                    *(__half2*)(CR + (size_t)r1 * N + c) = __floats2half2_rn(e0, e1);
                }
            }
        }
    }
}

// ---------------- launcher ----------------
extern "C" void kernel_launch(void* const* d_in, const int* in_sizes, int n_in,
                              void* d_out, int out_size)
{
    const float* x     = (const float*)d_in[0];
    const float* dt    = (const float*)d_in[1];
    const float* W1    = (const float*)d_in[2];
    const float* b1    = (const float*)d_in[3];
    const float* W2    = (const float*)d_in[4];
    const float* b2    = (const float*)d_in[5];
    const float* amps  = (const float*)d_in[6];
    const float* freqs = (const float*)d_in[7];
    const float* W3    = (const float*)d_in[8];
    const float* b3    = (const float*)d_in[9];
    const float* W4    = (const float*)d_in[10];
    const float* b4    = (const float*)d_in[11];
    float* out = (float*)d_out;

    const int Bn = 8192, DIN = 4096, HID = 4096, TWOF = 2048;

    float* full = out;
    float* encp = out + (size_t)Bn * DIN;
    float* encx = encp + (size_t)Bn * TWOF;

    __half *h, *xh, *encr, *wt;
    cudaGetSymbolAddress((void**)&h, g_h);
    cudaGetSymbolAddress((void**)&xh, g_xh);
    cudaGetSymbolAddress((void**)&encr, g_encr);
    cudaGetSymbolAddress((void**)&wt, g_wt);
    __half* WT1 = wt;
    __half* WT2 = WT1 + (size_t)DIN * HID;
    __half* WT3 = WT2 + (size_t)HID * TWOF;
    __half* WT4 = WT3 + (size_t)TWOF * HID;

    dim3 tb(32, 8);
    transpose_half<<<dim3(HID / 32, DIN / 64), tb>>>(W1, WT1, DIN, HID);
    transpose_half<<<dim3(TWOF / 32, HID / 64), tb>>>(W2, WT2, HID, TWOF);
    transpose_half<<<dim3(HID / 32, TWOF / 64), tb>>>(W3, WT3, TWOF, HID);
    transpose_half<<<dim3(DIN / 32, HID / 64), tb>>>(W4, WT4, HID, DIN);
    {
        int n4 = Bn * DIN / 4;
        half_copy<<<(n4 + 255) / 256, 256>>>(x, xh, n4);
    }

    cudaFuncSetAttribute((const void*)gemm_f16<0, 4096, 4096>, cudaFuncAttributeMaxDynamicSharedMemorySize, SMEM_DYN);
    cudaFuncSetAttribute((const void*)gemm_f16<1, 2048, 4096>, cudaFuncAttributeMaxDynamicSharedMemorySize, SMEM_DYN);
    cudaFuncSetAttribute((const void*)gemm_f16<0, 4096, 2048>, cudaFuncAttributeMaxDynamicSharedMemorySize, SMEM_DYN);
    cudaFuncSetAttribute((const void*)gemm_f16<2, 4096, 4096>, cudaFuncAttributeMaxDynamicSharedMemorySize, SMEM_DYN);

    dim3 blk(THREADS);

    gemm_f16<0, 4096, 4096><<<dim3(4096 / BN, Bn / BM), blk, SMEM_DYN>>>(
        xh, WT1, b1, (void*)h, nullptr, nullptr, nullptr, nullptr, nullptr);

    gemm_f16<1, 2048, 4096><<<dim3(2048 / BN, Bn / BM), blk, SMEM_DYN>>>(
        h, WT2, b2, (void*)encx, encp, encr, dt, amps, freqs);

    gemm_f16<0, 4096, 2048><<<dim3(4096 / BN, Bn / BM), blk, SMEM_DYN>>>(
        encr, WT3, b3, (void*)h, nullptr, nullptr, nullptr, nullptr, nullptr);

    gemm_f16<2, 4096, 4096><<<dim3(4096 / BN, Bn / BM), blk, SMEM_DYN>>>(
        h, WT4, b4, (void*)full, nullptr, nullptr, nullptr, nullptr, nullptr);
}

// round 17
// speedup vs baseline: 1.0158x; 1.0158x over previous
#include <cuda_runtime.h>
#include <cuda_fp16.h>
#include <cstdint>
#include <math.h>

// ---------------------------------------------------------------------------
// KoopmanAE, mma.sync FP16 (m16n8k16, f32 accum) + ldmatrix.
// CTA tile 128x128x64, 8 warps of 64x32, cp.async 3-stage, 2 CTAs/SM,
// cp.async interleaved between k-slices. (R14 GEMM, byte-identical.)
// R17: fused prepass (4 transposes + x->half), x-segment coverage FIXED
// (each thread now converts 4 float4; R16 covered only 1/4 of x).
// ---------------------------------------------------------------------------

#define BM 128
#define BN 128
#define BK 64
#define STAGES 3
#define THREADS 256

#define ALDB 144
#define STAGE_A_BYTES (128 * ALDB)
#define STAGE_BYTES (2 * STAGE_A_BYTES)
#define SMEM_DYN (STAGES * STAGE_BYTES)       // 110592

__device__ __half g_h[8192u * 4096u];
__device__ __half g_xh[8192u * 4096u];
__device__ __half g_encr[8192u * 2048u];
__device__ __half g_wt[4096u*4096u + 4096u*2048u + 2048u*4096u + 4096u*4096u];

// ---------------- helpers ----------------
__device__ __forceinline__ uint32_t smem_u32(const void* p) {
    uint32_t a;
    asm("{ .reg .u64 t; cvta.to.shared.u64 t, %1; cvt.u32.u64 %0, t; }" : "=r"(a) : "l"(p));
    return a;
}
__device__ __forceinline__ void cp16(uint32_t dst, const void* src) {
    asm volatile("cp.async.cg.shared.global [%0], [%1], 16;" :: "r"(dst), "l"(src));
}
#define CP_COMMIT() asm volatile("cp.async.commit_group;" ::: "memory")
#define CP_WAIT(n)  asm volatile("cp.async.wait_group %0;" :: "n"(n) : "memory")

__device__ __forceinline__ void ldsm4(uint32_t& r0, uint32_t& r1, uint32_t& r2,
                                      uint32_t& r3, uint32_t addr) {
    asm volatile("ldmatrix.sync.aligned.m8n8.x4.shared.b16 {%0,%1,%2,%3}, [%4];"
                 : "=r"(r0), "=r"(r1), "=r"(r2), "=r"(r3) : "r"(addr));
}

__device__ __forceinline__ void mma_f16(float d[4], const uint32_t a[4],
                                        uint32_t b0, uint32_t b1) {
    asm("mma.sync.aligned.m16n8k16.row.col.f32.f16.f16.f32 "
        "{%0,%1,%2,%3}, {%4,%5,%6,%7}, {%8,%9}, {%0,%1,%2,%3};"
        : "+f"(d[0]), "+f"(d[1]), "+f"(d[2]), "+f"(d[3])
        : "r"(a[0]), "r"(a[1]), "r"(a[2]), "r"(a[3]), "r"(b0), "r"(b1));
}

// ---------------- fused pre-pass ----------------
__device__ __forceinline__ void transpose_tile(const float* __restrict__ W,
                                               __half* __restrict__ WT,
                                               int K, int N, int bx, int by,
                                               float (*t)[33]) {
    const int nb = bx * 32, kb = by * 64;
    const int tx = threadIdx.x & 31, ty = threadIdx.x >> 5;   // 32 x 8
#pragma unroll
    for (int i = 0; i < 64; i += 8)
        t[ty + i][tx] = W[(size_t)(kb + ty + i) * N + nb + tx];
    __syncthreads();
#pragma unroll
    for (int i = 0; i < 32; i += 8) {
        const int n = nb + ty + i;
        __half2 v = __floats2half2_rn(t[2 * tx][ty + i], t[2 * tx + 1][ty + i]);
        *(__half2*)(WT + (size_t)n * K + kb + 2 * tx) = v;
    }
}

// Segments (blocks): [0,8192) T1 | [8192,12288) T2 | [12288,16384) T3
//                    | [16384,24576) T4 | [24576,32768) x->half (4 float4/thr)
__global__ void __launch_bounds__(256, 1)
prepass_fused(const float* __restrict__ W1, const float* __restrict__ W2,
              const float* __restrict__ W3, const float* __restrict__ W4,
              const float* __restrict__ x,
              __half* __restrict__ WT1, __half* __restrict__ WT2,
              __half* __restrict__ WT3, __half* __restrict__ WT4,
              __half* __restrict__ xh)
{
    __shared__ float t[64][33];
    const int bid = blockIdx.x;
    if (bid < 8192) {
        transpose_tile(W1, WT1, 4096, 4096, bid % 128, bid / 128, t);       // grid 128x64
    } else if (bid < 12288) {
        const int b = bid - 8192;
        transpose_tile(W2, WT2, 4096, 2048, b % 64, b / 64, t);             // grid 64x64
    } else if (bid < 16384) {
        const int b = bid - 12288;
        transpose_tile(W3, WT3, 2048, 4096, b % 128, b / 128, t);           // grid 128x32
    } else if (bid < 24576) {
        const int b = bid - 16384;
        transpose_tile(W4, WT4, 4096, 4096, b % 128, b / 128, t);           // grid 128x64
    } else {
        // x -> half: 8192*4096/4 = 8388608 float4 over 8192 blocks
        // -> 4 float4 per thread, grid-strided (coalesced within each pass)
        const int b = bid - 24576;
#pragma unroll
        for (int j = 0; j < 4; ++j) {
            const int i = (b + j * 8192) * 256 + (int)threadIdx.x;
            float4 v = ((const float4*)x)[i];
            __half2* o = (__half2*)(xh + (size_t)i * 4);
            o[0] = __floats2half2_rn(v.x, v.y);
            o[1] = __floats2half2_rn(v.z, v.w);
        }
    }
}

// ---------------- GEMM (byte-identical to R14) ----------------
// MODE 0: Ch = (half)tanh(acc+bias)
// MODE 1: Cf = acc+bias (enc_x), C2 = rotate (enc_pred), CR = (half)C2
// MODE 2: Cf = acc+bias
template <int MODE, int N, int K>
__global__ void __launch_bounds__(THREADS, 2)
gemm_f16(const __half* __restrict__ A, const __half* __restrict__ WT,
         const float* __restrict__ bias, void* __restrict__ Cv,
         float* __restrict__ C2, __half* __restrict__ CR,
         const float* __restrict__ dt, const float* __restrict__ amps,
         const float* __restrict__ freqs)
{
    extern __shared__ char sm[];
    const uint32_t sm_base = smem_u32(sm);

    const int tid    = threadIdx.x;
    const int wid    = tid >> 5;
    const int lane   = tid & 31;
    const int g      = lane >> 2;
    const int t      = lane & 3;
    const int warp_m = wid >> 2;
    const int warp_n = wid & 3;
    const int bm = blockIdx.y;
    const int bn = blockIdx.x;
    constexpr int KT = K / BK;

    const int rowc = tid >> 3;
    const int chnk = tid & 7;
    const __half* baseA = A  + (size_t)(bm * BM + rowc) * K + chnk * 8;
    const __half* baseB = WT + (size_t)(bn * BN + rowc) * K + chnk * 8;
    const uint32_t dA0 = (uint32_t)(rowc * ALDB + chnk * 16);
    const uint32_t dB0 = dA0 + STAGE_A_BYTES;

    const uint32_t a_lmb = (uint32_t)((warp_m * 64 + ((lane >> 3) & 1) * 8 + (lane & 7)) * ALDB
                                      + (lane >> 4) * 16);
    const uint32_t b_lmb = (uint32_t)(STAGE_A_BYTES
                                      + (warp_n * 32 + (lane >> 4) * 8 + (lane & 7)) * ALDB
                                      + ((lane >> 3) & 1) * 16);

#pragma unroll
    for (int p = 0; p < STAGES - 1; ++p) {
        const uint32_t sb = sm_base + p * STAGE_BYTES;
        const int ko = p * BK;
#pragma unroll
        for (int i = 0; i < 4; ++i)
            cp16(sb + dA0 + i * (32 * ALDB), baseA + (size_t)i * 32 * K + ko);
#pragma unroll
        for (int i = 0; i < 4; ++i)
            cp16(sb + dB0 + i * (32 * ALDB), baseB + (size_t)i * 32 * K + ko);
        CP_COMMIT();
    }

    float acc[4][4][4];
#pragma unroll
    for (int mi = 0; mi < 4; ++mi)
#pragma unroll
        for (int ni = 0; ni < 4; ++ni)
#pragma unroll
            for (int r = 0; r < 4; ++r) acc[mi][ni][r] = 0.0f;

    int stage_idx = 0;
    int write_idx = STAGES - 1;

    for (int kt = 0; kt < KT; ++kt) {
        CP_WAIT(STAGES - 2);
        __syncthreads();

        const int nt = kt + STAGES - 1;
        const bool ld = nt < KT;
        const uint32_t sb = sm_base + write_idx * STAGE_BYTES;
        const int ko = nt * BK;

        const uint32_t st_u = sm_base + stage_idx * STAGE_BYTES;
        const uint32_t a_base = st_u + a_lmb;
        const uint32_t b_base = st_u + b_lmb;

#pragma unroll
        for (int ks = 0; ks < 4; ++ks) {
            const uint32_t koff = (uint32_t)(ks * 32);
            uint32_t af[4][4];
#pragma unroll
            for (int mi = 0; mi < 4; ++mi)
                ldsm4(af[mi][0], af[mi][1], af[mi][2], af[mi][3],
                      a_base + (uint32_t)(mi * 16 * ALDB) + koff);
            uint32_t b00, b01, b10, b11, b20, b21, b30, b31;
            ldsm4(b00, b01, b10, b11, b_base + koff);
            ldsm4(b20, b21, b30, b31, b_base + (uint32_t)(16 * ALDB) + koff);

#pragma unroll
            for (int mi = 0; mi < 4; ++mi) {
                mma_f16(acc[mi][0], af[mi], b00, b01);
                mma_f16(acc[mi][1], af[mi], b10, b11);
                mma_f16(acc[mi][2], af[mi], b20, b21);
                mma_f16(acc[mi][3], af[mi], b30, b31);
            }

            if (ks == 0 && ld) {
#pragma unroll
                for (int i = 0; i < 4; ++i)
                    cp16(sb + dA0 + i * (32 * ALDB), baseA + (size_t)i * 32 * K + ko);
            } else if (ks == 1 && ld) {
#pragma unroll
                for (int i = 0; i < 2; ++i)
                    cp16(sb + dB0 + i * (32 * ALDB), baseB + (size_t)i * 32 * K + ko);
            } else if (ks == 2) {
                if (ld) {
#pragma unroll
                    for (int i = 2; i < 4; ++i)
                        cp16(sb + dB0 + i * (32 * ALDB), baseB + (size_t)i * 32 * K + ko);
                }
                CP_COMMIT();
            }
        }

        if (++stage_idx == STAGES) stage_idx = 0;
        if (++write_idx == STAGES) write_idx = 0;
    }

    // ---- epilogue ----
    const int row_base = bm * BM + warp_m * 64;
    const int col_base = bn * BN + warp_n * 32;

#pragma unroll
    for (int mi = 0; mi < 4; ++mi) {
        const int r0 = row_base + mi * 16 + g;
        const int r1 = r0 + 8;
        float dt0 = 0.f, dt1 = 0.f;
        if (MODE == 1) { dt0 = dt[r0]; dt1 = dt[r1]; }
#pragma unroll
        for (int ni = 0; ni < 4; ++ni) {
            const int c = col_base + ni * 8 + 2 * t;
            const float bv0 = bias[c];
            const float bv1 = bias[c + 1];
            float v00 = acc[mi][ni][0] + bv0;
            float v01 = acc[mi][ni][1] + bv1;
            float v10 = acc[mi][ni][2] + bv0;
            float v11 = acc[mi][ni][3] + bv1;

            if (MODE == 0) {
                __half* Ch = (__half*)Cv;
                *(__half2*)(Ch + (size_t)r0 * N + c) =
                    __floats2half2_rn(tanhf(v00), tanhf(v01));
                *(__half2*)(Ch + (size_t)r1 * N + c) =
                    __floats2half2_rn(tanhf(v10), tanhf(v11));
            } else {
                float* Cf = (float*)Cv;
                *(float2*)(Cf + (size_t)r0 * N + c) = make_float2(v00, v01);
                *(float2*)(Cf + (size_t)r1 * N + c) = make_float2(v10, v11);
            }

            if (MODE == 1) {
                const int f = c >> 1;
                const float af_ = amps[f];
                const float wf = freqs[f];
                {
                    float amp = __powf(af_, dt0);
                    float s, co;
                    sincosf(wf * dt0, &s, &co);
                    float cs = amp * co, ss = amp * s;
                    float e0 = cs * v00 - ss * v01;
                    float e1 = ss * v00 + cs * v01;
                    *(float2*)(C2 + (size_t)r0 * N + c) = make_float2(e0, e1);
                    *(__half2*)(CR + (size_t)r0 * N + c) = __floats2half2_rn(e0, e1);
                }
                {
                    float amp = __powf(af_, dt1);
                    float s, co;
                    sincosf(wf * dt1, &s, &co);
                    float cs = amp * co, ss = amp * s;
                    float e0 = cs * v10 - ss * v11;
                    float e1 = ss * v10 + cs * v11;
                    *(float2*)(C2 + (size_t)r1 * N + c) = make_float2(e0, e1);
                    *(__half2*)(CR + (size_t)r1 * N + c) = __floats2half2_rn(e0, e1);
                }
            }
        }
    }
}

// ---------------- launcher ----------------
extern "C" void kernel_launch(void* const* d_in, const int* in_sizes, int n_in,
                              void* d_out, int out_size)
{
    const float* x     = (const float*)d_in[0];
    const float* dt    = (const float*)d_in[1];
    const float* W1    = (const float*)d_in[2];
    const float* b1    = (const float*)d_in[3];
    const float* W2    = (const float*)d_in[4];
    const float* b2    = (const float*)d_in[5];
    const float* amps  = (const float*)d_in[6];
    const float* freqs = (const float*)d_in[7];
    const float* W3    = (const float*)d_in[8];
    const float* b3    = (const float*)d_in[9];
    const float* W4    = (const float*)d_in[10];
    const float* b4    = (const float*)d_in[11];
    float* out = (float*)d_out;

    const int Bn = 8192, DIN = 4096, HID = 4096, TWOF = 2048;

    float* full = out;
    float* encp = out + (size_t)Bn * DIN;
    float* encx = encp + (size_t)Bn * TWOF;

    __half *h, *xh, *encr, *wt;
    cudaGetSymbolAddress((void**)&h, g_h);
    cudaGetSymbolAddress((void**)&xh, g_xh);
    cudaGetSymbolAddress((void**)&encr, g_encr);
    cudaGetSymbolAddress((void**)&wt, g_wt);
    __half* WT1 = wt;
    __half* WT2 = WT1 + (size_t)DIN * HID;
    __half* WT3 = WT2 + (size_t)HID * TWOF;
    __half* WT4 = WT3 + (size_t)TWOF * HID;

    // one fused prepass launch: 4 transposes + x->half, all concurrent
    prepass_fused<<<32768, 256>>>(W1, W2, W3, W4, x, WT1, WT2, WT3, WT4, xh);

    cudaFuncSetAttribute((const void*)gemm_f16<0, 4096, 4096>, cudaFuncAttributeMaxDynamicSharedMemorySize, SMEM_DYN);
    cudaFuncSetAttribute((const void*)gemm_f16<1, 2048, 4096>, cudaFuncAttributeMaxDynamicSharedMemorySize, SMEM_DYN);
    cudaFuncSetAttribute((const void*)gemm_f16<0, 4096, 2048>, cudaFuncAttributeMaxDynamicSharedMemorySize, SMEM_DYN);
    cudaFuncSetAttribute((const void*)gemm_f16<2, 4096, 4096>, cudaFuncAttributeMaxDynamicSharedMemorySize, SMEM_DYN);

    dim3 blk(THREADS);

    gemm_f16<0, 4096, 4096><<<dim3(4096 / BN, Bn / BM), blk, SMEM_DYN>>>(
        xh, WT1, b1, (void*)h, nullptr, nullptr, nullptr, nullptr, nullptr);

    gemm_f16<1, 2048, 4096><<<dim3(2048 / BN, Bn / BM), blk, SMEM_DYN>>>(
        h, WT2, b2, (void*)encx, encp, encr, dt, amps, freqs);

    gemm_f16<0, 4096, 2048><<<dim3(4096 / BN, Bn / BM), blk, SMEM_DYN>>>(
        encr, WT3, b3, (void*)h, nullptr, nullptr, nullptr, nullptr, nullptr);

    gemm_f16<2, 4096, 4096><<<dim3(4096 / BN, Bn / BM), blk, SMEM_DYN>>>(
        h, WT4, b4, (void*)full, nullptr, nullptr, nullptr, nullptr, nullptr);
}